// round 13
// baseline (speedup 1.0000x reference)
#include <cuda_runtime.h>
#include <cuda_bf16.h>
#include <mma.h>

using namespace nvcuda;

// GNN_30064771072959: 2-layer GCN (DGL GraphConv, norm='both')
// R13: GEMM moved to tensor cores — wmma m16n16k8 TF32 with 3xTF32 splitting
//      (hi*hi + lo*hi + hi*lo) for ~fp32 accuracy. Agg = R7 4-edge unroll.

#define MAXN 131072
#define MAXE 1700000
#define SCAN_CHUNK 1024
#define MAXCHUNK (MAXN / SCAN_CHUNK)   // 128

__device__ float g_x[MAXN * 128];      // GEMM output (gather source)
__device__ float g_h[MAXN * 128];      // layer-1 hidden
__device__ int   g_col[MAXE];          // CSR col (= src) by dst
__device__ int   g_rowptr[MAXN + 1];
__device__ int   g_cursor[MAXN];
__device__ int   g_degout[MAXN];
__device__ int   g_degin[MAXN];
__device__ float g_nsrc[MAXN];
__device__ float g_ndst[MAXN];
__device__ int   g_part[MAXCHUNK];

__device__ __forceinline__ float to_tf32(float x) {
    unsigned u;
    asm("cvt.rna.tf32.f32 %0, %1;" : "=r"(u) : "f"(x));
    return __uint_as_float(u);
}
__device__ __forceinline__ void split_tf32(float x, float& hi, float& lo) {
    hi = to_tf32(x);
    lo = to_tf32(x - hi);
}

// ---------------------------------------------------------------- degrees
__global__ void k_zero(int n) {
    int i = blockIdx.x * blockDim.x + threadIdx.x;
    if (i < n) { g_degout[i] = 0; g_degin[i] = 0; }
}

__global__ void k_deg(const int* __restrict__ src, const int* __restrict__ dst, int E) {
    int e = blockIdx.x * blockDim.x + threadIdx.x;
    if (e < E) {
        atomicAdd(&g_degout[src[e]], 1);
        atomicAdd(&g_degin[dst[e]], 1);
    }
}

__global__ void k_norm(int n) {
    int i = blockIdx.x * blockDim.x + threadIdx.x;
    if (i < n) {
        g_nsrc[i] = rsqrtf((float)max(g_degout[i], 1));
        g_ndst[i] = rsqrtf((float)max(g_degin[i], 1));
    }
}

// ---------------------------------------------------------------- scan (rowptr)
__global__ void k_scan1(int n) {
    __shared__ int s[SCAN_CHUNK];
    int t = threadIdx.x;
    int i = blockIdx.x * SCAN_CHUNK + t;
    int v = (i < n) ? g_degin[i] : 0;
    s[t] = v;
    __syncthreads();
    #pragma unroll
    for (int off = 1; off < SCAN_CHUNK; off <<= 1) {
        int add = (t >= off) ? s[t - off] : 0;
        __syncthreads();
        s[t] += add;
        __syncthreads();
    }
    if (i < n) g_rowptr[i] = s[t] - v;          // local exclusive
    if (t == SCAN_CHUNK - 1) g_part[blockIdx.x] = s[t];
}

__global__ void k_scanfin(int n, int E, int nchunk) {
    __shared__ int s[MAXCHUNK];
    int t = threadIdx.x;
    if (t < MAXCHUNK) {
        int v = (t < nchunk) ? g_part[t] : 0;
        s[t] = v;
    }
    __syncthreads();
    if (t < MAXCHUNK) {
        #pragma unroll
        for (int off = 1; off < MAXCHUNK; off <<= 1) {
            int add = (t >= off) ? s[t - off] : 0;
            __syncthreads();
            s[t] += add;
            __syncthreads();
        }
    } else {
        #pragma unroll
        for (int off = 1; off < MAXCHUNK; off <<= 1) { __syncthreads(); __syncthreads(); }
    }
    __syncthreads();
    int i = blockIdx.x * blockDim.x + t;
    if (i < n) {
        int c = i >> 10;
        int base = (c == 0) ? 0 : s[c - 1];     // exclusive chunk offset
        int rp = g_rowptr[i] + base;
        g_rowptr[i] = rp;
        g_cursor[i] = rp;
    }
    if (i == 0) g_rowptr[n] = E;
}

__global__ void k_fill(const int* __restrict__ src, const int* __restrict__ dst, int E) {
    int e = blockIdx.x * blockDim.x + threadIdx.x;
    if (e < E) {
        int p = atomicAdd(&g_cursor[dst[e]], 1);
        g_col[p] = src[e];
    }
}

// ---------------------------------------------------------------- GEMM (tensor core, 3xTF32)
// x[n,128] = (A[n,128] * nsrc[n]) @ W[128,128]
// Block: 256 thr = 8 warps; block tile 64 rows x 128 cols.
// Warp w: rows (w&3)*16, cols (w>>2)*64 -> 4 acc fragments of 16x16.
// k staged in 16-chunks; A and W split into tf32 hi/lo in smem.
// 3xTF32: acc += a_hi*b_hi + a_lo*b_hi + a_hi*b_lo  (lo*lo term ~1e-6, dropped)
#define KC2 16
#define ALD 20     // As leading dim (pad: banks 4r+c all distinct)
#define WLD 132    // Ws leading dim (pad: <=2-way)
__global__ __launch_bounds__(256) void k_gemm(const float* __restrict__ A,
                                              const float* __restrict__ W,
                                              int n, int useH) {
    __shared__ float As_hi[64 * ALD], As_lo[64 * ALD];
    __shared__ float Ws_hi[KC2 * WLD], Ws_lo[KC2 * WLD];
    if (useH) A = g_h;

    int t    = threadIdx.x;
    int w    = t >> 5;
    int row0 = blockIdx.x * 64;
    int wr   = (w & 3) * 16;        // warp row offset in tile
    int wc   = (w >> 2) * 64;       // warp col offset

    wmma::fragment<wmma::accumulator, 16, 16, 8, float> acc[4];
    #pragma unroll
    for (int i = 0; i < 4; i++) wmma::fill_fragment(acc[i], 0.0f);

    const float4* Av = (const float4*)A;
    const float4* Wv = (const float4*)W;

    for (int kc = 0; kc < 128; kc += KC2) {
        __syncthreads();
        // stage A tile: 64 rows x 16 k = 256 float4; thread t handles one
        {
            int r = t >> 2, c4 = t & 3;
            int gr = row0 + r;
            float4 v = make_float4(0.f, 0.f, 0.f, 0.f);
            if (gr < n) {
                float ns = g_nsrc[gr];
                v = Av[gr * 32 + (kc >> 2) + c4];
                v.x *= ns; v.y *= ns; v.z *= ns; v.w *= ns;
            }
            int base = r * ALD + c4 * 4;
            split_tf32(v.x, As_hi[base + 0], As_lo[base + 0]);
            split_tf32(v.y, As_hi[base + 1], As_lo[base + 1]);
            split_tf32(v.z, As_hi[base + 2], As_lo[base + 2]);
            split_tf32(v.w, As_hi[base + 3], As_lo[base + 3]);
        }
        // stage W chunk: 16 k x 128 cols = 512 float4; thread t handles two
        #pragma unroll
        for (int i = 0; i < 2; i++) {
            int j = t + i * 256;                 // float4 index
            int k = j >> 5, c = (j & 31) * 4;
            float4 v = Wv[kc * 32 + j];
            int base = k * WLD + c;
            split_tf32(v.x, Ws_hi[base + 0], Ws_lo[base + 0]);
            split_tf32(v.y, Ws_hi[base + 1], Ws_lo[base + 1]);
            split_tf32(v.z, Ws_hi[base + 2], Ws_lo[base + 2]);
            split_tf32(v.w, Ws_hi[base + 3], Ws_lo[base + 3]);
        }
        __syncthreads();

        #pragma unroll
        for (int ks = 0; ks < KC2; ks += 8) {
            wmma::fragment<wmma::matrix_a, 16, 16, 8, wmma::precision::tf32, wmma::row_major> a_hi, a_lo;
            wmma::load_matrix_sync(a_hi, &As_hi[wr * ALD + ks], ALD);
            wmma::load_matrix_sync(a_lo, &As_lo[wr * ALD + ks], ALD);
            #pragma unroll
            for (int nt = 0; nt < 4; nt++) {
                wmma::fragment<wmma::matrix_b, 16, 16, 8, wmma::precision::tf32, wmma::row_major> b_hi, b_lo;
                wmma::load_matrix_sync(b_hi, &Ws_hi[ks * WLD + wc + nt * 16], WLD);
                wmma::load_matrix_sync(b_lo, &Ws_lo[ks * WLD + wc + nt * 16], WLD);
                wmma::mma_sync(acc[nt], a_hi, b_hi, acc[nt]);
                wmma::mma_sync(acc[nt], a_lo, b_hi, acc[nt]);
                wmma::mma_sync(acc[nt], a_hi, b_lo, acc[nt]);
            }
        }
    }

    // store 16x64 per warp; unguarded is safe: g_x/g_h sized MAXN(131072) rows
    // and max touched row = 1562*64+63 = 100031 < MAXN.
    #pragma unroll
    for (int nt = 0; nt < 4; nt++)
        wmma::store_matrix_sync(&g_x[(row0 + wr) * 128 + wc + nt * 16],
                                acc[nt], 128, wmma::mem_row_major);
}

// ---------------------------------------------------------------- aggregation
// warp per node; lane owns 4 cols (float4). 4-edge unroll (R7 exact).
__global__ __launch_bounds__(256) void k_agg(const float* __restrict__ bias,
                                             float* __restrict__ outp,
                                             int n, int relu, int toH) {
    int gw   = (blockIdx.x * blockDim.x + threadIdx.x) >> 5;
    int lane = threadIdx.x & 31;
    if (gw >= n) return;

    int beg = g_rowptr[gw];
    int end = g_rowptr[gw + 1];
    const float4* x4 = (const float4*)g_x;

    float4 acc = make_float4(0.f, 0.f, 0.f, 0.f);
    int j = beg;
    for (; j + 4 <= end; j += 4) {
        int s0 = g_col[j],     s1 = g_col[j + 1];
        int s2 = g_col[j + 2], s3 = g_col[j + 3];
        float4 v0 = __ldg(x4 + s0 * 32 + lane);
        float4 v1 = __ldg(x4 + s1 * 32 + lane);
        float4 v2 = __ldg(x4 + s2 * 32 + lane);
        float4 v3 = __ldg(x4 + s3 * 32 + lane);
        acc.x += (v0.x + v1.x) + (v2.x + v3.x);
        acc.y += (v0.y + v1.y) + (v2.y + v3.y);
        acc.z += (v0.z + v1.z) + (v2.z + v3.z);
        acc.w += (v0.w + v1.w) + (v2.w + v3.w);
    }
    for (; j < end; j++) {
        int s = g_col[j];
        float4 v = __ldg(x4 + s * 32 + lane);
        acc.x += v.x; acc.y += v.y; acc.z += v.z; acc.w += v.w;
    }

    float nd = g_ndst[gw];
    float4 b = __ldg((const float4*)bias + lane);
    float4 o;
    o.x = acc.x * nd + b.x;
    o.y = acc.y * nd + b.y;
    o.z = acc.z * nd + b.z;
    o.w = acc.w * nd + b.w;
    if (relu) {
        o.x = fmaxf(o.x, 0.f); o.y = fmaxf(o.y, 0.f);
        o.z = fmaxf(o.z, 0.f); o.w = fmaxf(o.w, 0.f);
    }
    float4* dst4 = toH ? (float4*)g_h : (float4*)outp;
    dst4[gw * 32 + lane] = o;
}

// ---------------------------------------------------------------- launch
extern "C" void kernel_launch(void* const* d_in, const int* in_sizes, int n_in,
                              void* d_out, int out_size) {
    const float* feature = (const float*)d_in[0];
    const int*   src     = (const int*)d_in[1];
    const int*   dst     = (const int*)d_in[2];
    const float* W1      = (const float*)d_in[3];
    const float* b1      = (const float*)d_in[4];
    const float* W2      = (const float*)d_in[5];
    const float* b2      = (const float*)d_in[6];
    float* out = (float*)d_out;

    int N = in_sizes[0] / 128;
    int E = in_sizes[1];
    int nchunk = (N + SCAN_CHUNK - 1) / SCAN_CHUNK;

    int gemm_grid = (N + 63) / 64;
    int agg_grid  = (N * 32 + 255) / 256;

    // launches 1-3: degrees + norms (all gemm0 needs besides inputs)
    k_zero<<<(N + 255) / 256, 256>>>(N);
    k_deg<<<(E + 255) / 256, 256>>>(src, dst, E);
    k_norm<<<(N + 255) / 256, 256>>>(N);

    // launch 4 (ncu-profiled): layer-0 GEMM
    k_gemm<<<gemm_grid, 256>>>(feature, W1, N, 0);

    // CSR build (needed only by k_agg)
    k_scan1<<<nchunk, SCAN_CHUNK>>>(N);
    k_scanfin<<<(N + 1023) / 1024, 1024>>>(N, E, nchunk);
    k_fill<<<(E + 255) / 256, 256>>>(src, dst, E);

    // layer 0 aggregation: relu -> g_h
    k_agg<<<agg_grid, 256>>>(b1, out, N, 1, 1);

    // layer 1: no activation -> d_out
    k_gemm<<<gemm_grid, 256>>>(nullptr, W2, N, 1);
    k_agg<<<agg_grid, 256>>>(b2, out, N, 0, 0);
}

// round 14
// speedup vs baseline: 1.5198x; 1.5198x over previous
#include <cuda_runtime.h>
#include <cuda_bf16.h>

// GNN_30064771072959: 2-layer GCN (DGL GraphConv, norm='both')
// R14: R7 champion GEMM + (a) __launch_bounds__(256,3) for 3 blocks/SM
//      (regs 88->85, occ 23%->35%), (b) w-operands loaded as ulonglong2
//      directly from smem (kills 4 forced MOVs per 2-kstep). Agg = R7 exact.

#define MAXN 131072
#define MAXE 1700000
#define SCAN_CHUNK 1024
#define MAXCHUNK (MAXN / SCAN_CHUNK)   // 128

typedef unsigned long long u64;

__device__ float g_x[MAXN * 128];      // GEMM output (gather source)
__device__ float g_h[MAXN * 128];      // layer-1 hidden
__device__ int   g_col[MAXE];          // CSR col (= src) by dst
__device__ int   g_rowptr[MAXN + 1];
__device__ int   g_cursor[MAXN];
__device__ int   g_degout[MAXN];
__device__ int   g_degin[MAXN];
__device__ float g_nsrc[MAXN];
__device__ float g_ndst[MAXN];
__device__ int   g_part[MAXCHUNK];

__device__ __forceinline__ u64 fma2(u64 a, u64 b, u64 c) {
    u64 d;
    asm("fma.rn.f32x2 %0, %1, %2, %3;" : "=l"(d) : "l"(a), "l"(b), "l"(c));
    return d;
}
__device__ __forceinline__ u64 splat2(float a) {
    u64 d;
    asm("mov.b64 %0, {%1, %1};" : "=l"(d) : "f"(a));
    return d;
}

// ---------------------------------------------------------------- degrees
__global__ void k_zero(int n) {
    int i = blockIdx.x * blockDim.x + threadIdx.x;
    if (i < n) { g_degout[i] = 0; g_degin[i] = 0; }
}

__global__ void k_deg(const int* __restrict__ src, const int* __restrict__ dst, int E) {
    int e = blockIdx.x * blockDim.x + threadIdx.x;
    if (e < E) {
        atomicAdd(&g_degout[src[e]], 1);
        atomicAdd(&g_degin[dst[e]], 1);
    }
}

__global__ void k_norm(int n) {
    int i = blockIdx.x * blockDim.x + threadIdx.x;
    if (i < n) {
        g_nsrc[i] = rsqrtf((float)max(g_degout[i], 1));
        g_ndst[i] = rsqrtf((float)max(g_degin[i], 1));
    }
}

// ---------------------------------------------------------------- scan (rowptr)
__global__ void k_scan1(int n) {
    __shared__ int s[SCAN_CHUNK];
    int t = threadIdx.x;
    int i = blockIdx.x * SCAN_CHUNK + t;
    int v = (i < n) ? g_degin[i] : 0;
    s[t] = v;
    __syncthreads();
    #pragma unroll
    for (int off = 1; off < SCAN_CHUNK; off <<= 1) {
        int add = (t >= off) ? s[t - off] : 0;
        __syncthreads();
        s[t] += add;
        __syncthreads();
    }
    if (i < n) g_rowptr[i] = s[t] - v;          // local exclusive
    if (t == SCAN_CHUNK - 1) g_part[blockIdx.x] = s[t];
}

__global__ void k_scanfin(int n, int E, int nchunk) {
    __shared__ int s[MAXCHUNK];
    int t = threadIdx.x;
    if (t < MAXCHUNK) {
        int v = (t < nchunk) ? g_part[t] : 0;
        s[t] = v;
    }
    __syncthreads();
    if (t < MAXCHUNK) {
        #pragma unroll
        for (int off = 1; off < MAXCHUNK; off <<= 1) {
            int add = (t >= off) ? s[t - off] : 0;
            __syncthreads();
            s[t] += add;
            __syncthreads();
        }
    } else {
        #pragma unroll
        for (int off = 1; off < MAXCHUNK; off <<= 1) { __syncthreads(); __syncthreads(); }
    }
    __syncthreads();
    int i = blockIdx.x * blockDim.x + t;
    if (i < n) {
        int c = i >> 10;
        int base = (c == 0) ? 0 : s[c - 1];     // exclusive chunk offset
        int rp = g_rowptr[i] + base;
        g_rowptr[i] = rp;
        g_cursor[i] = rp;
    }
    if (i == 0) g_rowptr[n] = E;
}

__global__ void k_fill(const int* __restrict__ src, const int* __restrict__ dst, int E) {
    int e = blockIdx.x * blockDim.x + threadIdx.x;
    if (e < E) {
        int p = atomicAdd(&g_cursor[dst[e]], 1);
        g_col[p] = src[e];
    }
}

// ---------------------------------------------------------------- GEMM (f32x2)
// x[n,128] = (A[n,128] * nsrc[n]) @ W[128,128]
// Block: 256 thr -> 64 rows x 128 cols. Warp w owns rows w*8..w*8+7 (a-loads
// are smem BROADCASTS); lane owns cols lane*4..lane*4+3 as two f32x2 accums.
// smem: Ws[32][128] (16KB) + As[64][34] pad-2 (8.5KB). 3 blocks/SM.
#define AS_STRIDE 34
__global__ __launch_bounds__(256, 3) void k_gemm(const float* __restrict__ A,
                                                 const float* __restrict__ W,
                                                 int n, int useH) {
    __shared__ float Ws[32 * 128];
    __shared__ float As[64 * AS_STRIDE];
    if (useH) A = g_h;

    int t    = threadIdx.x;
    int lane = t & 31;
    int w    = t >> 5;          // warp id: rows [w*8, w*8+8)
    int row0 = blockIdx.x * 64;

    u64 acc[8][2];
    #pragma unroll
    for (int i = 0; i < 8; i++) { acc[i][0] = 0ull; acc[i][1] = 0ull; }

    const float4* Av = (const float4*)A;

    for (int kc = 0; kc < 128; kc += 32) {
        __syncthreads();
        // load W rows [kc, kc+32): 4096 floats, coalesced float4
        #pragma unroll
        for (int i = 0; i < 4; i++) {
            int idx4 = t + i * 256;
            ((float4*)Ws)[idx4] = ((const float4*)W)[kc * 32 + idx4];
        }
        // load scaled A tile 64x32 (row-major, stride AS_STRIDE)
        #pragma unroll
        for (int i = 0; i < 2; i++) {
            int j = t + i * 256;            // 512 float4 = 64 rows x 8 chunks
            int r = j >> 3, c = j & 7;
            int gr = row0 + r;
            float4 v = make_float4(0.f, 0.f, 0.f, 0.f);
            if (gr < n) {
                float ns = g_nsrc[gr];
                v = Av[gr * 32 + (kc >> 2) + c];
                v.x *= ns; v.y *= ns; v.z *= ns; v.w *= ns;
            }
            int base = r * AS_STRIDE + c * 4;
            As[base + 0] = v.x; As[base + 1] = v.y;
            As[base + 2] = v.z; As[base + 3] = v.w;
        }
        __syncthreads();

        #pragma unroll
        for (int kk = 0; kk < 32; kk += 2) {
            // broadcast a-pairs (2 k-steps) for this warp's 8 rows
            float2 a2[8];
            #pragma unroll
            for (int i = 0; i < 8; i++)
                a2[i] = *(const float2*)&As[(w * 8 + i) * AS_STRIDE + kk];

            // w-operands straight from smem as u64 pairs (no MOV repacking)
            ulonglong2 wv0 = *(const ulonglong2*)&Ws[kk * 128 + lane * 4];
            ulonglong2 wv1 = *(const ulonglong2*)&Ws[(kk + 1) * 128 + lane * 4];

            #pragma unroll
            for (int i = 0; i < 8; i++) {
                u64 a0 = splat2(a2[i].x);
                acc[i][0] = fma2(a0, wv0.x, acc[i][0]);
                acc[i][1] = fma2(a0, wv0.y, acc[i][1]);
            }
            #pragma unroll
            for (int i = 0; i < 8; i++) {
                u64 a1 = splat2(a2[i].y);
                acc[i][0] = fma2(a1, wv1.x, acc[i][0]);
                acc[i][1] = fma2(a1, wv1.y, acc[i][1]);
            }
        }
    }

    #pragma unroll
    for (int i = 0; i < 8; i++) {
        int gr = row0 + w * 8 + i;
        if (gr < n) {
            float2 lo = *(float2*)&acc[i][0];
            float2 hi = *(float2*)&acc[i][1];
            *(float4*)&g_x[gr * 128 + lane * 4] = make_float4(lo.x, lo.y, hi.x, hi.y);
        }
    }
}

// ---------------------------------------------------------------- aggregation
// warp per node; lane owns 4 cols (float4). 4-edge unroll (R7 exact).
__global__ __launch_bounds__(256) void k_agg(const float* __restrict__ bias,
                                             float* __restrict__ outp,
                                             int n, int relu, int toH) {
    int gw   = (blockIdx.x * blockDim.x + threadIdx.x) >> 5;
    int lane = threadIdx.x & 31;
    if (gw >= n) return;

    int beg = g_rowptr[gw];
    int end = g_rowptr[gw + 1];
    const float4* x4 = (const float4*)g_x;

    float4 acc = make_float4(0.f, 0.f, 0.f, 0.f);
    int j = beg;
    for (; j + 4 <= end; j += 4) {
        int s0 = g_col[j],     s1 = g_col[j + 1];
        int s2 = g_col[j + 2], s3 = g_col[j + 3];
        float4 v0 = __ldg(x4 + s0 * 32 + lane);
        float4 v1 = __ldg(x4 + s1 * 32 + lane);
        float4 v2 = __ldg(x4 + s2 * 32 + lane);
        float4 v3 = __ldg(x4 + s3 * 32 + lane);
        acc.x += (v0.x + v1.x) + (v2.x + v3.x);
        acc.y += (v0.y + v1.y) + (v2.y + v3.y);
        acc.z += (v0.z + v1.z) + (v2.z + v3.z);
        acc.w += (v0.w + v1.w) + (v2.w + v3.w);
    }
    for (; j < end; j++) {
        int s = g_col[j];
        float4 v = __ldg(x4 + s * 32 + lane);
        acc.x += v.x; acc.y += v.y; acc.z += v.z; acc.w += v.w;
    }

    float nd = g_ndst[gw];
    float4 b = __ldg((const float4*)bias + lane);
    float4 o;
    o.x = acc.x * nd + b.x;
    o.y = acc.y * nd + b.y;
    o.z = acc.z * nd + b.z;
    o.w = acc.w * nd + b.w;
    if (relu) {
        o.x = fmaxf(o.x, 0.f); o.y = fmaxf(o.y, 0.f);
        o.z = fmaxf(o.z, 0.f); o.w = fmaxf(o.w, 0.f);
    }
    float4* dst4 = toH ? (float4*)g_h : (float4*)outp;
    dst4[gw * 32 + lane] = o;
}

// ---------------------------------------------------------------- launch
extern "C" void kernel_launch(void* const* d_in, const int* in_sizes, int n_in,
                              void* d_out, int out_size) {
    const float* feature = (const float*)d_in[0];
    const int*   src     = (const int*)d_in[1];
    const int*   dst     = (const int*)d_in[2];
    const float* W1      = (const float*)d_in[3];
    const float* b1      = (const float*)d_in[4];
    const float* W2      = (const float*)d_in[5];
    const float* b2      = (const float*)d_in[6];
    float* out = (float*)d_out;

    int N = in_sizes[0] / 128;
    int E = in_sizes[1];
    int nchunk = (N + SCAN_CHUNK - 1) / SCAN_CHUNK;

    int gemm_grid = (N + 63) / 64;
    int agg_grid  = (N * 32 + 255) / 256;

    // launches 1-3: degrees + norms (all gemm0 needs besides inputs)
    k_zero<<<(N + 255) / 256, 256>>>(N);
    k_deg<<<(E + 255) / 256, 256>>>(src, dst, E);
    k_norm<<<(N + 255) / 256, 256>>>(N);

    // launch 4 (ncu-profiled): layer-0 GEMM
    k_gemm<<<gemm_grid, 256>>>(feature, W1, N, 0);

    // CSR build (needed only by k_agg)
    k_scan1<<<nchunk, SCAN_CHUNK>>>(N);
    k_scanfin<<<(N + 1023) / 1024, 1024>>>(N, E, nchunk);
    k_fill<<<(E + 255) / 256, 256>>>(src, dst, E);

    // layer 0 aggregation: relu -> g_h
    k_agg<<<agg_grid, 256>>>(b1, out, N, 1, 1);

    // layer 1: no activation -> d_out
    k_gemm<<<gemm_grid, 256>>>(nullptr, W2, N, 1);
    k_agg<<<agg_grid, 256>>>(b2, out, N, 0, 0);
}